// round 9
// baseline (speedup 1.0000x reference)
#include <cuda_runtime.h>
#include <cuda_fp16.h>
#include <cstdint>
#include <math.h>

// ---------------------------------------------------------------------------
// Problem constants
// ---------------------------------------------------------------------------
#define NTOK      49
#define DIM       384
#define NHEADS    12
#define HD        32
#define NWIN      4096
#define NMASK     1024
#define M_TOTAL   (NWIN * NTOK)     // 200704
#define QKV_N     (3 * DIM)         // 1152
#define KTOT      384
#define ATTN_SCALE 0.17677669529663687f
#define BM_STR    2404              // padded row (floats, 16B multiple)

// Scratch (__device__ globals; allocation-free rule)
__device__ __align__(128) __half g_qkvh[(size_t)M_TOTAL * QKV_N];
__device__ __align__(128) __half g_xh [(size_t)M_TOTAL * DIM];
__device__ __align__(128) __half g_ah [(size_t)M_TOTAL * DIM];
__device__ __align__(128) __half g_wqh[QKV_N * DIM];
__device__ __align__(128) __half g_wph[DIM * DIM];
__device__ __align__(128) float  g_bias12[NHEADS * BM_STR];     // rpb gathered, padded
__device__ __align__(128) float  g_maskp[(size_t)NMASK * BM_STR]; // mask rows, padded

// ---------------------------------------------------------------------------
// Helpers
// ---------------------------------------------------------------------------
__device__ __forceinline__ uint32_t smem_u32(const void* p) {
    uint32_t a;
    asm("{ .reg .u64 t; cvta.to.shared.u64 t, %1; cvt.u32.u64 %0, t; }" : "=r"(a) : "l"(p));
    return a;
}

__device__ __forceinline__ void cpa16(uint32_t dst, const void* src) {
    asm volatile("cp.async.cg.shared.global [%0], [%1], 16;" :: "r"(dst), "l"(src) : "memory");
}
#define CP_COMMIT() asm volatile("cp.async.commit_group;" ::: "memory")
#define CP_WAIT1()  asm volatile("cp.async.wait_group 1;" ::: "memory")
#define CP_WAIT0()  asm volatile("cp.async.wait_group 0;" ::: "memory")

__device__ __forceinline__ void mma_f16(float* d, const uint32_t* a, const uint32_t* b) {
    asm volatile(
        "mma.sync.aligned.m16n8k16.row.col.f32.f16.f16.f32 "
        "{%0,%1,%2,%3}, {%4,%5,%6,%7}, {%8,%9}, {%0,%1,%2,%3};"
        : "+f"(d[0]), "+f"(d[1]), "+f"(d[2]), "+f"(d[3])
        : "r"(a[0]), "r"(a[1]), "r"(a[2]), "r"(a[3]), "r"(b[0]), "r"(b[1]));
}

__device__ __forceinline__ void ldsm_x4(uint32_t* r, uint32_t addr) {
    asm volatile("ldmatrix.sync.aligned.m8n8.x4.shared.b16 {%0,%1,%2,%3}, [%4];"
                 : "=r"(r[0]), "=r"(r[1]), "=r"(r[2]), "=r"(r[3]) : "r"(addr));
}
__device__ __forceinline__ void ldsm_x4_t(uint32_t* r, uint32_t addr) {
    asm volatile("ldmatrix.sync.aligned.m8n8.x4.trans.shared.b16 {%0,%1,%2,%3}, [%4];"
                 : "=r"(r[0]), "=r"(r[1]), "=r"(r[2]), "=r"(r[3]) : "r"(addr));
}

// ---------------------------------------------------------------------------
// fp16 tensor-core GEMM (unchanged, proven)
// ---------------------------------------------------------------------------
#define BKH      32
#define NSTAGE   3
#define KITERS   (KTOT / BKH)
#define SROWW    20
#define STAGEW   (128 * SROWW)
#define SMEM_TOT (NSTAGE * STAGEW * 2 * 4)

template <typename OutT>
__global__ __launch_bounds__(256, 2)
void gemm_mma_kernel(const __half* __restrict__ A,
                     const __half* __restrict__ W,
                     const float* __restrict__ bias,
                     OutT* __restrict__ C,
                     int Ntot) {
    extern __shared__ __align__(16) uint32_t sm[];
    uint32_t* Asm = sm;
    uint32_t* Bsm = sm + NSTAGE * STAGEW;

    const int tid  = threadIdx.x;
    const int warp = tid >> 5;
    const int lane = tid & 31;
    const int gid  = lane >> 2;
    const int tig  = lane & 3;
    const int wm   = warp & 1;
    const int wn   = warp >> 1;
    const int mb   = blockIdx.y * 128;
    const int nb   = blockIdx.x * 128;

    const int aLane = ((lane & 7) + 8 * ((lane >> 3) & 1)) * SROWW + 4 * (lane >> 4);
    const int bLane = ((lane & 7) + 8 * (lane >> 4)) * SROWW + 4 * ((lane >> 3) & 1);

    auto load_stage = [&](int s, int kt) {
        uint32_t* as = Asm + s * STAGEW;
        uint32_t* bs = Bsm + s * STAGEW;
        const int k0 = kt * BKH;
        #pragma unroll
        for (int i = 0; i < 2; i++) {
            const int f = tid + i * 256;
            const int m = f >> 2;
            const int g = f & 3;
            cpa16(smem_u32(as + m * SROWW + g * 4), A + (size_t)(mb + m) * KTOT + k0 + g * 8);
            cpa16(smem_u32(bs + m * SROWW + g * 4), W + (size_t)(nb + m) * KTOT + k0 + g * 8);
        }
    };

    float acc[4][4][4];
    #pragma unroll
    for (int mt = 0; mt < 4; mt++)
        #pragma unroll
        for (int nt = 0; nt < 4; nt++)
            #pragma unroll
            for (int r = 0; r < 4; r++) acc[mt][nt][r] = 0.0f;

    load_stage(0, 0); CP_COMMIT();
    load_stage(1, 1); CP_COMMIT();

    for (int kt = 0; kt < KITERS; ++kt) {
        CP_WAIT1();
        __syncthreads();

        const int s = kt % NSTAGE;
        if (kt + 2 < KITERS) load_stage((kt + 2) % NSTAGE, kt + 2);
        CP_COMMIT();

        const uint32_t aS = smem_u32(Asm + s * STAGEW);
        const uint32_t bS = smem_u32(Bsm + s * STAGEW);

        #pragma unroll
        for (int ks = 0; ks < 2; ks++) {
            const int kw = ks * 8;
            uint32_t af[4][4], bf[4][2];
            #pragma unroll
            for (int mt = 0; mt < 4; mt++) {
                const int base = (wm * 64 + mt * 16) * SROWW + kw + aLane;
                ldsm_x4(af[mt], aS + base * 4);
            }
            #pragma unroll
            for (int np = 0; np < 2; np++) {
                uint32_t q[4];
                const int base = (wn * 32 + np * 16) * SROWW + kw + bLane;
                ldsm_x4(q, bS + base * 4);
                bf[2 * np + 0][0] = q[0]; bf[2 * np + 0][1] = q[1];
                bf[2 * np + 1][0] = q[2]; bf[2 * np + 1][1] = q[3];
            }
            #pragma unroll
            for (int mt = 0; mt < 4; mt++)
                #pragma unroll
                for (int nt = 0; nt < 4; nt++)
                    mma_f16(acc[mt][nt], af[mt], bf[nt]);
        }
    }

    #pragma unroll
    for (int mt = 0; mt < 4; mt++) {
        const int row = mb + wm * 64 + mt * 16 + gid;
        #pragma unroll
        for (int nt = 0; nt < 4; nt++) {
            const int col = nb + wn * 32 + nt * 8 + 2 * tig;
            const float b0 = bias[col], b1 = bias[col + 1];
            if constexpr (sizeof(OutT) == 4) {
                float2 v0 = make_float2(acc[mt][nt][0] + b0, acc[mt][nt][1] + b1);
                float2 v1 = make_float2(acc[mt][nt][2] + b0, acc[mt][nt][3] + b1);
                *reinterpret_cast<float2*>((float*)C + (size_t)row * Ntot + col)       = v0;
                *reinterpret_cast<float2*>((float*)C + (size_t)(row + 8) * Ntot + col) = v1;
            } else {
                __half2 h0 = __floats2half2_rn(acc[mt][nt][0] + b0, acc[mt][nt][1] + b1);
                __half2 h1 = __floats2half2_rn(acc[mt][nt][2] + b0, acc[mt][nt][3] + b1);
                *reinterpret_cast<__half2*>((__half*)C + (size_t)row * Ntot + col)       = h0;
                *reinterpret_cast<__half2*>((__half*)C + (size_t)(row + 8) * Ntot + col) = h1;
            }
        }
    }
}

// ---------------------------------------------------------------------------
// Prep kernels
// ---------------------------------------------------------------------------
__global__ void f2h_kernel(const float4* __restrict__ in,
                           uint2* __restrict__ out, int n4) {
    int i = blockIdx.x * blockDim.x + threadIdx.x;
    if (i < n4) {
        float4 v = in[i];
        __half2 h0 = __floats2half2_rn(v.x, v.y);
        __half2 h1 = __floats2half2_rn(v.z, v.w);
        uint2 u;
        u.x = *reinterpret_cast<uint32_t*>(&h0);
        u.y = *reinterpret_cast<uint32_t*>(&h1);
        out[i] = u;
    }
}

__global__ void bias_prep_kernel(const float* __restrict__ rpb,
                                 const int* __restrict__ rel_idx,
                                 float* __restrict__ out) {
    const int h = blockIdx.x;
    for (int e = threadIdx.x; e < BM_STR; e += 128)
        out[h * BM_STR + e] = (e < NTOK * NTOK) ? rpb[rel_idx[e] * NHEADS + h] : 0.0f;
}

__global__ void mask_pad_kernel(const float* __restrict__ mask,
                                float* __restrict__ out) {
    const int m = blockIdx.x;
    const float* src = mask + (size_t)m * (NTOK * NTOK);
    float* dst = out + (size_t)m * BM_STR;
    for (int e = threadIdx.x; e < BM_STR; e += 128)
        dst[e] = (e < NTOK * NTOK) ? src[e] : 0.0f;
}

// ---------------------------------------------------------------------------
// Window attention v5: one CTA per (mask-row m, head h), 4 windows pipelined
// (windows m, m+1024, m+2048, m+3072 share mask row m).
// ---------------------------------------------------------------------------
// Dynamic smem layout (bytes):
#define OFF_QK   0          // 2 buffers x (Q 5120 + K 5120) = 20480; Ph aliases
#define OFF_V    20480      // 2 buffers x 5120 = 10240
#define OFF_SF   30720      // 49*57*4 = 11172 -> 11184
#define OFF_BS   41904      // 2404*4 = 9616
#define OFF_MS   51520      // 9616
#define ATT_SMEM 61136

__global__ __launch_bounds__(128, 3)
void win_attn_kernel(const __half* __restrict__ qkv,
                     const float* __restrict__ bias12,
                     const float* __restrict__ maskp,
                     __half* __restrict__ attout) {
    extern __shared__ __align__(16) char smem[];
    const int m = blockIdx.x / NHEADS;
    const int h = blockIdx.x % NHEADS;
    const int tid  = threadIdx.x;
    const int warp = tid >> 5;
    const int lane = tid & 31;
    const int gid  = lane >> 2;
    const int tig  = lane & 3;

    float* SfP = reinterpret_cast<float*>(smem + OFF_SF);
    float* BsP = reinterpret_cast<float*>(smem + OFF_BS);
    float* MsP = reinterpret_cast<float*>(smem + OFF_MS);

    auto prefetch_qkv = [&](int b) {
        const __half* basep = qkv + (size_t)(b * NMASK + m) * (NTOK * QKV_N) + h * HD;
        char* qdst = smem + OFF_QK + (b & 1) * 10240;
        char* kdst = qdst + 5120;
        char* vdst = smem + OFF_V + (b & 1) * 5120;
        for (int idx = tid; idx < 3 * NTOK * 4; idx += 128) {
            const int mm = idx / (NTOK * 4);
            const int rem = idx - mm * (NTOK * 4);
            const int i = rem >> 2;
            const int g = rem & 3;
            char* dst = ((mm == 0) ? qdst : (mm == 1) ? kdst : vdst) + i * 80 + g * 16;
            cpa16(smem_u32(dst), basep + (size_t)i * QKV_N + mm * DIM + g * 8);
        }
    };

    // Group 0: bias row + mask row + qkv window 0
    for (int idx = tid; idx < BM_STR / 4; idx += 128)
        cpa16(smem_u32(BsP + idx * 4), bias12 + h * BM_STR + idx * 4);
    for (int idx = tid; idx < BM_STR / 4; idx += 128)
        cpa16(smem_u32(MsP + idx * 4), maskp + (size_t)m * BM_STR + idx * 4);
    prefetch_qkv(0);
    CP_COMMIT();
    prefetch_qkv(1);
    CP_COMMIT();

    // Zero pad rows 49..63 of Q/K/V in both buffers (disjoint from loads)
    const uint4 z4 = make_uint4(0, 0, 0, 0);
    for (int idx = tid; idx < 450; idx += 128) {
        const int buf = idx / 225;
        const int r2 = idx - buf * 225;
        const int a = r2 / 75;
        const int rem = r2 - a * 75;
        const int r = 49 + rem / 5;
        const int g = rem % 5;
        char* dst = (a < 2) ? smem + OFF_QK + buf * 10240 + a * 5120 + r * 80 + g * 16
                            : smem + OFF_V + buf * 5120 + r * 80 + g * 16;
        *reinterpret_cast<uint4*>(dst) = z4;
    }

    const int aL = ((lane & 7) + 8 * ((lane >> 3) & 1)) * 20 + 4 * (lane >> 4);
    const int bL = ((lane & 7) + 8 * (lane >> 4)) * 20 + 4 * ((lane >> 3) & 1);
    const int aLp = ((lane & 7) + 8 * ((lane >> 3) & 1)) * 36 + 4 * (lane >> 4);

    #pragma unroll 1
    for (int b = 0; b < 4; ++b) {
        if (b < 3) { CP_WAIT1(); } else { CP_WAIT0(); }
        __syncthreads();

        const uint32_t QS = smem_u32(smem + OFF_QK + (b & 1) * 10240);
        const uint32_t KS = QS + 5120;
        const uint32_t VS = smem_u32(smem + OFF_V + (b & 1) * 5120);
        __half* PhP = reinterpret_cast<__half*>(smem + OFF_QK + (b & 1) * 10240);
        const uint32_t PS = QS;

        // ---- Scores: S = Q K^T ----
        float acc[8][4];
        #pragma unroll
        for (int a = 0; a < 8; a++)
            #pragma unroll
            for (int r = 0; r < 4; r++) acc[a][r] = 0.0f;

        #pragma unroll
        for (int ks = 0; ks < 2; ks++) {
            uint32_t af[4];
            ldsm_x4(af, QS + (uint32_t)(warp * 16 * 20 + ks * 8 + aL) * 4);
            #pragma unroll
            for (int nb = 0; nb < 4; nb++) {
                uint32_t q[4];
                ldsm_x4(q, KS + (uint32_t)(nb * 16 * 20 + ks * 8 + bL) * 4);
                mma_f16(acc[nb * 2 + 0], af, q + 0);
                mma_f16(acc[nb * 2 + 1], af, q + 2);
            }
        }

        // scores + scale + bias + mask (smem)
        {
            const int i0 = warp * 16 + gid;
            #pragma unroll
            for (int nt = 0; nt < 8; nt++) {
                const int j = nt * 8 + 2 * tig;
                if (j < NTOK) {
                    #pragma unroll
                    for (int rr = 0; rr < 2; rr++) {
                        const int i = i0 + rr * 8;
                        if (i < NTOK) {
                            const int e = i * NTOK + j;
                            SfP[i * 57 + j] = fmaf(acc[nt][rr * 2], ATTN_SCALE,
                                                   BsP[e] + MsP[e]);
                            if (j + 1 < NTOK)
                                SfP[i * 57 + j + 1] = fmaf(acc[nt][rr * 2 + 1], ATTN_SCALE,
                                                           BsP[e + 1] + MsP[e + 1]);
                        }
                    }
                }
            }
        }
        __syncthreads();   // Sf complete; Q/K dead -> Ph region reusable

        // ---- Softmax (threads 0..48) || P pad-zeroing (threads 49..127) ----
        if (tid < NTOK) {
            const int i = tid;
            float mx = -1e30f;
            #pragma unroll 7
            for (int j = 0; j < NTOK; j++) mx = fmaxf(mx, SfP[i * 57 + j]);
            float s = 0.0f;
            #pragma unroll 7
            for (int j = 0; j < NTOK; j++) {
                const float e = __expf(SfP[i * 57 + j] - mx);
                SfP[i * 57 + j] = e;
                s += e;
            }
            const float inv = 1.0f / s;
            #pragma unroll 7
            for (int j = 0; j < NTOK; j++)
                PhP[i * 72 + j] = __float2half_rn(SfP[i * 57 + j] * inv);
            #pragma unroll
            for (int j = NTOK; j < 56; j++)
                PhP[i * 72 + j] = __ushort_as_half((unsigned short)0);
        } else {
            for (int idx = tid - NTOK; idx < 233; idx += 128 - NTOK) {
                int r, c;
                if (idx < 135) { r = 49 + idx / 9; c = (idx % 9) * 8; }
                else           { const int q = idx - 135; r = q >> 1; c = 56 + (q & 1) * 8; }
                *reinterpret_cast<uint4*>(&PhP[r * 72 + c]) = z4;
            }
        }
        __syncthreads();

        // ---- PV: O = P V ----
        float pacc[4][4];
        #pragma unroll
        for (int a = 0; a < 4; a++)
            #pragma unroll
            for (int r = 0; r < 4; r++) pacc[a][r] = 0.0f;

        #pragma unroll
        for (int ks = 0; ks < 4; ks++) {
            uint32_t pf[4];
            ldsm_x4(pf, PS + (uint32_t)(warp * 16 * 36 + ks * 8 + aLp) * 4);
            uint32_t v0[4], v1[4];
            const int vLk = ((lane & 7) + 8 * ((lane >> 3) & 1)) * 20 + 4 * (lane >> 4);
            ldsm_x4_t(v0, VS + (uint32_t)(ks * 16 * 20 + vLk) * 4);
            ldsm_x4_t(v1, VS + (uint32_t)(ks * 16 * 20 + 8 + vLk) * 4);
            mma_f16(pacc[0], pf, v0 + 0);
            mma_f16(pacc[1], pf, v0 + 2);
            mma_f16(pacc[2], pf, v1 + 0);
            mma_f16(pacc[3], pf, v1 + 2);
        }
        __syncthreads();   // all reads of buf done -> safe to prefetch b+2

        if (b < 2) prefetch_qkv(b + 2);
        CP_COMMIT();

        // ---- Store O (fp16) for window b*1024 + m ----
        {
            __half* ob = attout + (size_t)(b * NMASK + m) * (NTOK * DIM) + h * HD;
            const int i0 = warp * 16 + gid;
            #pragma unroll
            for (int nt = 0; nt < 4; nt++) {
                const int d = nt * 8 + 2 * tig;
                #pragma unroll
                for (int rr = 0; rr < 2; rr++) {
                    const int i = i0 + rr * 8;
                    if (i < NTOK) {
                        __half2 hv = __floats2half2_rn(pacc[nt][rr * 2], pacc[nt][rr * 2 + 1]);
                        *reinterpret_cast<__half2*>(ob + (size_t)i * DIM + d) = hv;
                    }
                }
            }
        }
    }
}

// ---------------------------------------------------------------------------
// Launch
// ---------------------------------------------------------------------------
extern "C" void kernel_launch(void* const* d_in, const int* in_sizes, int n_in,
                              void* d_out, int out_size) {
    const float* x      = (const float*)d_in[0];
    const float* mask   = (const float*)d_in[1];
    const float* rpb    = (const float*)d_in[2];
    const float* qkv_w  = (const float*)d_in[3];
    const float* qkv_b  = (const float*)d_in[4];
    const float* proj_w = (const float*)d_in[5];
    const float* proj_b = (const float*)d_in[6];
    const int*   rel_i  = (const int*)d_in[7];
    float* out = (float*)d_out;

    __half *qkvh, *xh, *ah, *wqh, *wph;
    float *biasb, *maskb;
    cudaGetSymbolAddress((void**)&qkvh, g_qkvh);
    cudaGetSymbolAddress((void**)&xh,  g_xh);
    cudaGetSymbolAddress((void**)&ah,  g_ah);
    cudaGetSymbolAddress((void**)&wqh, g_wqh);
    cudaGetSymbolAddress((void**)&wph, g_wph);
    cudaGetSymbolAddress((void**)&biasb, g_bias12);
    cudaGetSymbolAddress((void**)&maskb, g_maskp);

    cudaFuncSetAttribute(gemm_mma_kernel<__half>,
                         cudaFuncAttributeMaxDynamicSharedMemorySize, SMEM_TOT);
    cudaFuncSetAttribute(gemm_mma_kernel<float>,
                         cudaFuncAttributeMaxDynamicSharedMemorySize, SMEM_TOT);
    cudaFuncSetAttribute(win_attn_kernel,
                         cudaFuncAttributeMaxDynamicSharedMemorySize, ATT_SMEM);

    // prep: conversions + padded bias/mask tables
    {
        int n4 = (M_TOTAL * DIM) / 4;
        f2h_kernel<<<(n4 + 255) / 256, 256>>>((const float4*)x, (uint2*)xh, n4);
        int w4 = (QKV_N * DIM) / 4;
        f2h_kernel<<<(w4 + 255) / 256, 256>>>((const float4*)qkv_w, (uint2*)wqh, w4);
        int p4 = (DIM * DIM) / 4;
        f2h_kernel<<<(p4 + 255) / 256, 256>>>((const float4*)proj_w, (uint2*)wph, p4);
        bias_prep_kernel<<<NHEADS, 128>>>(rpb, rel_i, biasb);
        mask_pad_kernel<<<NMASK, 128>>>(mask, maskb);
    }

    // 1) QKV projection -> fp16 qkv
    {
        dim3 grid(QKV_N / 128, M_TOTAL / 128);
        gemm_mma_kernel<__half><<<grid, 256, SMEM_TOT>>>(xh, wqh, qkv_b, qkvh, QKV_N);
    }

    // 2) Windowed attention: 4 windows per CTA, pipelined
    win_attn_kernel<<<NMASK * NHEADS, 128, ATT_SMEM>>>(qkvh, biasb, maskb, ah);

    // 3) Output projection -> fp32 d_out
    {
        dim3 grid(DIM / 128, M_TOTAL / 128);
        gemm_mma_kernel<float><<<grid, 256, SMEM_TOT>>>(ah, wph, proj_b, out, DIM);
    }
}